// round 16
// baseline (speedup 1.0000x reference)
#include <cuda_runtime.h>
#include <math.h>

#define NPIX   4096
#define NMODE  64
#define NSEQ   64
#define NCH    256

typedef unsigned long long u64;

__device__ __forceinline__ u64 pk(float a, float b){
  u64 r; asm("mov.b64 %0,{%1,%2};" : "=l"(r) : "f"(a), "f"(b)); return r;
}
__device__ __forceinline__ float2 up(u64 v){
  float2 r; asm("mov.b64 {%0,%1},%2;" : "=f"(r.x), "=f"(r.y) : "l"(v)); return r;
}
__device__ __forceinline__ void fma2(u64& d, u64 a, u64 b){
  asm("fma.rn.f32x2 %0,%1,%2,%0;" : "+l"(d) : "l"(a), "l"(b));
}

// branch-free erf, Abramowitz-Stegun 7.1.26, max abs err 1.5e-7
__device__ __forceinline__ float erf_fast(float x){
  float ax = fabsf(x);
  float t  = __frcp_rn(1.0f + 0.3275911f*ax);
  float y  = t*(0.254829592f + t*(-0.284496736f + t*(1.421413741f +
             t*(-1.453152027f + t*1.061405429f))));
  float r  = 1.0f - y*__expf(-ax*ax);
  return copysignf(r, x);
}

// ---------------- scratch ----------------
__device__ __align__(16) float2 g_vf [NSEQ*4*NMODE];
__device__ __align__(16) float2 g_G2 [8*8*16*64];       // [g1][g2][ci*4+cj][m]
__device__ __align__(16) float  g_l2s[16*32*32];
__device__ __align__(16) float2 g_vlf[NSEQ*NCH*NMODE];
__device__ __align__(16) float2 g_ufT[NCH*NMODE*NSEQ];  // [ch][m][n]
__device__ __align__(16) float2 g_w1t[NMODE*NCH*32];    // [m][ci][co], P-scaled
__device__ __align__(16) float  g_s1t[NCH*32];          // [ci][co]
__device__ __align__(16) float2 g_uf2p[2][NSEQ*NMODE*32];  // partials, [n][m][co]
__device__ __align__(16) float2 g_sk1p[2][NSEQ*NMODE*32];
__device__ __align__(16) float  g_x1 [NSEQ*32*NPIX];
__device__ __align__(16) float2 g_x1f[NSEQ*32*NMODE];

__device__ __forceinline__ void tw_init(float* twc, float* tws, u64* twp, int tid){
  if (tid < 64){
    float a = 0.09817477042468103f * (float)tid;
    float cc = cosf(a), ss = sinf(a);
    twc[tid]=cc; tws[tid]=ss;
    if (twp) twp[tid]=pk(cc,ss);
  }
}

// ---------------- K1: fwd DFT of v (0-63) + G matrix (64-127) + weight transpose (128-191) ----
__global__ __launch_bounds__(256) void k_pre(const float* __restrict__ v,
                      const float* __restrict__ qwr, const float* __restrict__ qwi,
                      const float* __restrict__ kwr, const float* __restrict__ kwi,
                      const float* __restrict__ u1wr, const float* __restrict__ u1wi,
                      const float* __restrict__ s1w){
  int tid = threadIdx.x;
  if (blockIdx.x < 64){
    __shared__ float twc[64], tws[64];
    __shared__ u64   twp[64];
    __shared__ float2 sC[4*8*64];
    int chv=tid>>6, c=tid&63;
    tw_init(twc,tws,twp,tid);
    __syncthreads();
    const float* x = v + (size_t)(blockIdx.x*4 + chv)*NPIX + c;
    u64 C2[8];
    #pragma unroll
    for (int ky=0;ky<8;ky++) C2[ky]=0ull;
    for (int r=0;r<64;r++){
      float xv = __ldg(x + r*64);
      u64 x2 = pk(xv,xv);
      #pragma unroll
      for (int ky=0;ky<8;ky++) fma2(C2[ky], x2, twp[(ky*r)&63]);
    }
    #pragma unroll
    for (int ky=0;ky<8;ky++) sC[(chv*8+ky)*64 + c] = up(C2[ky]);
    __syncthreads();
    {
      int md = tid&63, ky2 = md>>3, kx = md&7;
      float re=0.f, im=0.f;
      const float2* Crow = sC + (chv*8+ky2)*64;
      #pragma unroll 8
      for (int cc=0;cc<64;cc++){
        float2 t = Crow[cc];
        int j=(kx*cc)&63;
        re += t.x*twc[j] - t.y*tws[j];
        im -= t.y*twc[j] + t.x*tws[j];
      }
      g_vf[(size_t)(blockIdx.x*4+chv)*64 + md] = make_float2(re,im);
    }
  } else if (blockIdx.x < 128){
    // G: 4 chunks x 16 modes, all 256 threads compute
    int bid2 = blockIdx.x - 64;
    int gq = bid2>>3, gk = bid2&7;
    __shared__ float2 sQ[4][32][16];
    __shared__ float2 sK[4][32][16];
    for (int mc=0;mc<4;mc++){
      __syncthreads();
      int mb = mc*16;
      for (int i=tid;i<2048;i+=256){
        int ci=i>>9, d=(i>>4)&31, mm=i&15;
        int iq = (ci*256 + gq*32+d)*64 + mb+mm;
        int ik = (ci*256 + gk*32+d)*64 + mb+mm;
        sQ[ci][d][mm] = make_float2(qwr[iq], qwi[iq]);
        sK[ci][d][mm] = make_float2(kwr[ik], kwi[ik]);
      }
      __syncthreads();
      {
        int cicj = tid>>4, mm = tid&15;
        int ci = cicj>>2, cj = cicj&3;
        int m = mb+mm;
        float re=0.f, im=0.f;
        if (m==0){
          #pragma unroll 8
          for (int d=0;d<32;d++) re += sQ[ci][d][0].x * sK[cj][d][0].x;
        } else {
          #pragma unroll 8
          for (int d=0;d<32;d++){
            float2 q=sQ[ci][d][mm], kk=sK[cj][d][mm];
            re += q.x*kk.x + q.y*kk.y;
            im += q.y*kk.x - q.x*kk.y;
          }
          float wm = ((m&7)==0) ? 0.5f : 2.0f;
          re*=wm; im*=wm;
        }
        g_G2[((size_t)(gq*8+gk)*16 + cicj)*64 + m] = make_float2(re,im);
      }
    }
  } else {
    int m = blockIdx.x - 128;
    bool kx0 = ((m&7)==0), m0 = (m==0);
    float pm = (!m0 && kx0) ? 0.5f : 1.0f;
    for (int idx=tid; idx<8192; idx+=256){
      int ci = idx>>5, co = idx&31;
      int widx = (ci*32+co)*64 + m;
      g_w1t[(size_t)(m*256+ci)*32+co] = make_float2(u1wr[widx]*pm, u1wi[widx]*pm);
    }
    if (m==0){
      for (int idx=tid; idx<8192; idx+=256){
        int ci = idx>>5, co = idx&31;
        g_s1t[ci*32+co] = s1w[co*256+ci];
      }
    }
  }
}

// ---------------- K2: vmix (blocks 0-127, m-halved) + attention scores (blocks 128-255) ----
__global__ __launch_bounds__(256) void k_mid(const float* __restrict__ vwr, const float* __restrict__ vwi){
  int tid=threadIdx.x;
  if (blockIdx.x < 128){
    int b = blockIdx.x;
    int ng = b>>3, cog = (b>>1)&3, mh = b&1;
    __shared__ float2 sv[1024];
    int n0 = ng*4;
    for (int i=tid;i<1024;i+=256) sv[i] = g_vf[(size_t)n0*256 + i];
    __syncthreads();
    for (int p=tid; p<1024; p+=256){
      int co_l = p>>4, m2 = mh*16 + (p&15), m = m2*2;
      int co = cog*64 + co_l;
      float2 wrv[4], wiv[4];
      #pragma unroll
      for (int ci=0;ci<4;ci++){
        int wix = ((ci<<8)+co)*64 + m;
        wrv[ci] = *(const float2*)&vwr[wix];
        wiv[ci] = *(const float2*)&vwi[wix];
      }
      #pragma unroll
      for (int nl=0;nl<4;nl++){
        float re0=0.f,im0=0.f,re1=0.f,im1=0.f;
        #pragma unroll
        for (int ci=0;ci<4;ci++){
          float2 a0 = sv[nl*256+ci*64+m], a1 = sv[nl*256+ci*64+m+1];
          re0 += a0.x*wrv[ci].x - a0.y*wiv[ci].x;  im0 += a0.x*wiv[ci].x + a0.y*wrv[ci].x;
          re1 += a1.x*wrv[ci].y - a1.y*wiv[ci].y;  im1 += a1.x*wiv[ci].y + a1.y*wrv[ci].y;
        }
        float4 st = make_float4(re0,im0,re1,im1);
        *(float4*)&g_vlf[(size_t)(n0+nl)*16384 + co*64 + m] = st;
      }
    }
  } else {
    int idx = blockIdx.x - 128;
    int bh = idx>>3, g1 = idx&7;
    int b = bh>>3, hh = bh&7;
    int nbase = b*32 + hh*4;
    int g2 = tid>>5, lane = tid&31;
    const u64* Vf = (const u64*)g_vf;
    const u64* Gp = (const u64*)g_G2 + (size_t)(g1*8+g2)*1024;
    u64 sc[4][4];
    #pragma unroll
    for (int j1=0;j1<4;j1++)
      #pragma unroll
      for (int i2=0;i2<4;i2++) sc[j1][i2]=0ull;
    #pragma unroll
    for (int ml=0; ml<2; ml++){
      int m = lane + 32*ml;
      u64 vfl[4][4];
      #pragma unroll
      for (int j=0;j<4;j++)
        #pragma unroll
        for (int ci=0;ci<4;ci++)
          vfl[j][ci] = Vf[(size_t)(nbase+j)*256 + ci*64 + m];
      u64 Gl[4][4];
      #pragma unroll
      for (int ci=0;ci<4;ci++)
        #pragma unroll
        for (int cj=0;cj<4;cj++)
          Gl[ci][cj] = Gp[(ci*4+cj)*64 + m];
      u64 Wl[4][4];
      #pragma unroll
      for (int i2=0;i2<4;i2++)
        #pragma unroll
        for (int ci=0;ci<4;ci++){
          float re=0.f, im=0.f;
          #pragma unroll
          for (int cj=0;cj<4;cj++){
            float2 vv = up(vfl[i2][cj]);
            float2 gg = up(Gl[ci][cj]);
            re += vv.x*gg.x + vv.y*gg.y;
            im += vv.x*gg.y - vv.y*gg.x;
          }
          Wl[i2][ci] = pk(re, -im);
        }
      #pragma unroll
      for (int j1=0;j1<4;j1++)
        #pragma unroll
        for (int i2=0;i2<4;i2++)
          #pragma unroll
          for (int ci=0;ci<4;ci++)
            fma2(sc[j1][i2], vfl[j1][ci], Wl[i2][ci]);
    }
    float scf[16];
    #pragma unroll
    for (int j1=0;j1<4;j1++)
      #pragma unroll
      for (int i2=0;i2<4;i2++){
        float2 a = up(sc[j1][i2]);
        float s = a.x + a.y;
        #pragma unroll
        for (int o=16;o;o>>=1) s += __shfl_xor_sync(0xffffffffu, s, o);
        scf[j1*4+i2] = s;
      }
    if (lane < 16){
      int j1 = lane>>2, i2 = lane&3;
      g_l2s[bh*1024 + (j1*8+g1)*32 + i2*8+g2] = scf[lane];
    }
  }
}

// ---------------- K3: fused softmax + U = A @ val ----------------
// grid (16 head, 8 dg, 4 sg), 256 thr
__global__ __launch_bounds__(256) void k_attn_u(){
  int bh = blockIdx.x, dg = blockIdx.y, sg = blockIdx.z;
  int b = bh>>3, hh = bh&7;
  const float2* Vh = g_vlf + (size_t)(b*32 + hh*4)*16384;
  __shared__ float  sL [256];
  __shared__ float2 sA2[256];
  int tid = threadIdx.x;
  {
    int sl=tid>>5, t=tid&31;
    sL[tid] = g_l2s[bh*1024 + (sg*8+sl)*32 + t] * 2.9802322387695312e-8f;
  }
  __syncthreads();
  {
    int w=tid>>5, lane=tid&31;
    float x = sL[w*32+lane];
    float mx = x;
    #pragma unroll
    for (int o=16;o;o>>=1) mx = fmaxf(mx, __shfl_xor_sync(0xffffffffu, mx, o));
    float e = expf(x-mx);
    float sm = e;
    #pragma unroll
    for (int o=16;o;o>>=1) sm += __shfl_xor_sync(0xffffffffu, sm, o);
    float pr = e/sm;
    sA2[w*32+lane] = make_float2(pr,pr);
  }
  __syncthreads();
  int d = dg*4 + (tid>>6);
  int m = tid&63;
  u64 acc[8];
  #pragma unroll
  for (int s=0;s<8;s++) acc[s]=0ull;
  const float2* vp = Vh + d*64 + m;
  #pragma unroll 1
  for (int t=0;t<32;t+=4){
    u64 v0 = *(const u64*)(vp + (size_t)(t+0)*2048);
    u64 v1 = *(const u64*)(vp + (size_t)(t+1)*2048);
    u64 v2 = *(const u64*)(vp + (size_t)(t+2)*2048);
    u64 v3 = *(const u64*)(vp + (size_t)(t+3)*2048);
    #pragma unroll
    for (int s=0;s<8;s++){
      fma2(acc[s], *(const u64*)&sA2[s*32+t+0], v0);
      fma2(acc[s], *(const u64*)&sA2[s*32+t+1], v1);
      fma2(acc[s], *(const u64*)&sA2[s*32+t+2], v2);
      fma2(acc[s], *(const u64*)&sA2[s*32+t+3], v3);
    }
  }
  int chb = hh*32 + d;
  float2* dst = g_ufT + ((size_t)chb*64 + m)*64 + b*32 + sg*8;
  #pragma unroll
  for (int s=0;s<8;s++) dst[s] = up(acc[s]);
}

// ---------------- K4: per-mode GEMM 256->32 (u1 with P projection) + s1 skip ----------------
// grid (64 m, 4 ns, 2 cs), 256 thr; 16 n/block (1 pair per warp); coalesced stores
__global__ __launch_bounds__(256) void k_u1(){
  int m = blockIdx.x, ns = blockIdx.y, cs = blockIdx.z;
  bool m0 = (m==0);
  int tid = threadIdx.x, l = tid&31, w = tid>>5;
  __shared__ u64   sAx[256], sAy[256];  // [cil][pair8]
  __shared__ float2 sW[1024];
  __shared__ float  sS[1024];
  u64 cRe=0ull, cIm=0ull, kRe=0ull, kIm=0ull;
  int cbase = cs*128;
  for (int ci0=cbase; ci0<cbase+128; ci0+=32){
    __syncthreads();
    {
      int cil = tid>>3, p = tid&7;
      float4 a2 = *(const float4*)&g_ufT[((size_t)(ci0+cil)*64 + m)*64 + ns*16 + p*2];
      sAx[cil*8+p] = pk(a2.x, a2.z);
      sAy[cil*8+p] = pk(a2.y, a2.w);
    }
    #pragma unroll
    for (int k=0;k<2;k++){
      int idx = tid + k*256;
      int cil = idx>>4, cp = idx&15;
      float4 w2 = *(const float4*)&g_w1t[(size_t)(m*256 + ci0+cil)*32 + cp*2];
      sW[cil*32 + cp*2]   = make_float2(w2.x, w2.y);
      sW[cil*32 + cp*2+1] = make_float2(w2.z, w2.w);
      float2 s2 = *(const float2*)&g_s1t[(ci0+cil)*32 + cp*2];
      sS[cil*32 + cp*2]   = s2.x;
      sS[cil*32 + cp*2+1] = s2.y;
    }
    __syncthreads();
    #pragma unroll 8
    for (int cil=0; cil<32; cil++){
      float2 wv = sW[cil*32+l];
      float swv = sS[cil*32+l];
      u64 wxs = pk(wv.x, wv.x);
      u64 wys = pk(wv.y, wv.y);
      u64 wyn = m0 ? 0ull : pk(-wv.y, -wv.y);
      u64 wxY = m0 ? 0ull : wxs;
      u64 sws = pk(swv, swv);
      u64 X = sAx[cil*8 + w];
      u64 Y = sAy[cil*8 + w];
      fma2(cRe, X, wxs); fma2(cRe, Y, wyn);
      fma2(cIm, X, wys); fma2(cIm, Y, wxY);
      fma2(kRe, X, sws);
      fma2(kIm, Y, sws);
    }
  }
  float2* uf2 = g_uf2p[cs];
  float2* sk1 = g_sk1p[cs];
  {
    float2 re=up(cRe), im=up(cIm);
    float2 sre=up(kRe), sim=up(kIm);
    int n0 = ns*16 + w*2;
    uf2[((size_t)(n0  )*64+m)*32+l] = make_float2(re.x, im.x);
    uf2[((size_t)(n0+1)*64+m)*32+l] = make_float2(re.y, im.y);
    sk1[((size_t)(n0  )*64+m)*32+l] = make_float2(sre.x, sim.x);
    sk1[((size_t)(n0+1)*64+m)*32+l] = make_float2(sre.y, sim.y);
  }
}

// ---------------- K5: synthesis + gelu + skip -> x1, fused forward DFT -> x1f ----------------
__global__ __launch_bounds__(256) void k_x1(const float* __restrict__ s1b){
  __shared__ float twc[64], tws[64];
  __shared__ u64   twp[64];
  __shared__ float2 sF1[256], sF2[256];
  __shared__ float2 sC[4*8*64];
  int tid=threadIdx.x, chv=tid>>6, c=tid&63;
  int n = blockIdx.x>>3, cg = blockIdx.x&7;
  int ch = cg*4 + chv;
  tw_init(twc,tws,twp,tid);
  {
    int chl = tid&3, mm = tid>>2;
    size_t ix = ((size_t)n*64 + mm)*32 + cg*4 + chl;
    float2 a0 = g_uf2p[0][ix], a1 = g_uf2p[1][ix];
    sF1[mm*4+chl] = make_float2(a0.x+a1.x, a0.y+a1.y);
    float2 b0 = g_sk1p[0][ix], b1 = g_sk1p[1][ix];
    sF2[mm*4+chl] = make_float2(b0.x+b1.x, b0.y+b1.y);
  }
  __syncthreads();
  u64 U1p[8], U2p[8];
  #pragma unroll
  for (int ky=0;ky<8;ky++){
    float2 f1=sF1[(ky*8)*4+chv], f2=sF2[(ky*8)*4+chv];
    float u1x=f1.x, u1y=f1.y, u2x=f2.x, u2y=f2.y;
    #pragma unroll
    for (int kx=1;kx<8;kx++){
      int j=(kx*c)&63; float tc=twc[j], ts=tws[j];
      f1=sF1[(ky*8+kx)*4+chv]; f2=sF2[(ky*8+kx)*4+chv];
      u1x += 2.f*(f1.x*tc - f1.y*ts); u1y += 2.f*(f1.x*ts + f1.y*tc);
      u2x += 2.f*(f2.x*tc - f2.y*ts); u2y += 2.f*(f2.x*ts + f2.y*tc);
    }
    U1p[ky]=pk(u1x,u1y); U2p[ky]=pk(u2x,u2y);
  }
  u64 C2[8];
  #pragma unroll
  for (int ky=0;ky<8;ky++) C2[ky]=0ull;
  float bias = s1b[ch&31];
  float* gx = g_x1 + ((size_t)n*32 + ch)*NPIX + c;
  const float inv = 1.0f/4096.0f;
  for (int r=0;r<64;r++){
    u64 wp[8];
    #pragma unroll
    for (int ky=0;ky<8;ky++) wp[ky]=twp[(ky*r)&63];
    u64 a1=0ull, a2=0ull;
    #pragma unroll
    for (int ky=0;ky<8;ky++){ fma2(a1,U1p[ky],wp[ky]); fma2(a2,U2p[ky],wp[ky]); }
    float2 v1=up(a1), v2=up(a2);
    float y1=(v1.x - v1.y)*inv;
    float y2=(v2.x - v2.y)*inv;
    float g = 0.5f*y1*(1.f+erf_fast(y1*0.70710678118654752f));
    float val = g + y2 + bias;
    gx[r*64] = val;
    u64 vp2 = pk(val,val);
    #pragma unroll
    for (int ky=0;ky<8;ky++) fma2(C2[ky], vp2, wp[ky]);
  }
  #pragma unroll
  for (int ky=0;ky<8;ky++) sC[(chv*8+ky)*64 + c] = up(C2[ky]);
  __syncthreads();
  {
    int md=tid&63, ky2=md>>3, kx=md&7;
    float re=0.f, im=0.f;
    const float2* Crow = sC + (chv*8+ky2)*64;
    #pragma unroll 8
    for (int cc=0;cc<64;cc++){
      float2 t = Crow[cc];
      int j=(kx*cc)&63;
      re += t.x*twc[j] - t.y*tws[j];
      im -= t.y*twc[j] + t.x*tws[j];
    }
    g_x1f[((size_t)n*32 + ch)*64 + md] = make_float2(re,im);
  }
}

// ---------------- K6: u2 spectral conv + synthesis + conv1x1 skip ----------------
__global__ __launch_bounds__(256) void k_final(const float* __restrict__ u2wr, const float* __restrict__ u2wi,
                        const float* __restrict__ s2w, const float* __restrict__ s2b,
                        float* __restrict__ out){
  int n = blockIdx.x;
  __shared__ float twc[64], tws[64];
  __shared__ u64   twp[64];
  __shared__ float2 sXF[2048];
  __shared__ float2 sF[256];
  __shared__ float2 T[4*512];
  __shared__ u64 sw2[128];
  __shared__ float sbv[4];
  int tid=threadIdx.x;
  tw_init(twc,tws,twp,tid);
  for (int i=tid;i<2048;i+=256) sXF[i] = g_x1f[(size_t)n*2048 + i];
  if (tid<128){ float w=s2w[tid]; sw2[tid]=pk(w,w); }
  if (tid<4) sbv[tid]=s2b[tid];
  __syncthreads();
  {
    int o=tid>>6, m=tid&63;
    float re=0.f, im=0.f;
    #pragma unroll 8
    for (int ci=0;ci<32;ci++){
      float2 a = sXF[ci*64+m];
      int wix = ((ci*4+o)<<6)+m;
      float br=u2wr[wix], bi=u2wi[wix];
      re += a.x*br - a.y*bi;
      im += a.x*bi + a.y*br;
    }
    sF[tid]=make_float2(re,im);
  }
  __syncthreads();
  for (int id=tid; id<2048; id+=256){
    int o=id>>9, rem=id&511, r=rem>>3, kx=rem&7;
    float re=0.f, im=0.f;
    #pragma unroll
    for (int ky=0;ky<8;ky++){
      int j=(ky*r)&63; float cc=twc[j], ss=tws[j];
      float2 f=sF[o*64+ky*8+kx];
      re += f.x*cc - f.y*ss; im += f.x*ss + f.y*cc;
    }
    T[id]=make_float2(re,im);
  }
  __syncthreads();
  const float4* gx4 = (const float4*)(g_x1 + (size_t)n*32*NPIX);
  float* go = out + (size_t)n*4*NPIX;
  const float inv = 1.0f/4096.0f;
  {
    int q = blockIdx.y*256 + tid;
    int p0 = q*4, r = p0>>6, cb = p0&63;
    float ybuf[4][4];
    #pragma unroll
    for (int j=0;j<4;j++){
      int cc = cb+j;
      u64 a[4]={0ull,0ull,0ull,0ull};
      #pragma unroll
      for (int kx=1;kx<8;kx++){
        u64 wv = twp[(kx*cc)&63];
        #pragma unroll
        for (int o=0;o<4;o++) fma2(a[o], *(const u64*)&T[o*512 + r*8 + kx], wv);
      }
      #pragma unroll
      for (int o=0;o<4;o++){
        float2 v = up(a[o]);
        ybuf[o][j] = T[o*512 + r*8].x + 2.f*(v.x - v.y);
      }
    }
    u64 s01[4]={0ull,0ull,0ull,0ull}, s23[4]={0ull,0ull,0ull,0ull};
    #pragma unroll 8
    for (int ci=0;ci<32;ci++){
      float4 xv = __ldg(gx4 + ci*1024 + q);
      u64 x01 = pk(xv.x,xv.y), x23 = pk(xv.z,xv.w);
      #pragma unroll
      for (int o=0;o<4;o++){
        u64 wv = sw2[o*32+ci];
        fma2(s01[o], wv, x01);
        fma2(s23[o], wv, x23);
      }
    }
    #pragma unroll
    for (int o=0;o<4;o++){
      float2 p01=up(s01[o]), p23=up(s23[o]);
      float bo = sbv[o];
      float4 r4;
      r4.x = ybuf[o][0]*inv + p01.x + bo;
      r4.y = ybuf[o][1]*inv + p01.y + bo;
      r4.z = ybuf[o][2]*inv + p23.x + bo;
      r4.w = ybuf[o][3]*inv + p23.y + bo;
      *(float4*)(go + o*NPIX + p0) = r4;
    }
  }
}

// ---------------- launch ----------------
extern "C" void kernel_launch(void* const* d_in, const int* in_sizes, int n_in,
                              void* d_out, int out_size){
  const float* v   = (const float*)d_in[0];
  const float* qwr = (const float*)d_in[1];
  const float* qwi = (const float*)d_in[2];
  const float* kwr = (const float*)d_in[3];
  const float* kwi = (const float*)d_in[4];
  const float* vwr = (const float*)d_in[5];
  const float* vwi = (const float*)d_in[6];
  const float* u1wr= (const float*)d_in[7];
  const float* u1wi= (const float*)d_in[8];
  const float* u2wr= (const float*)d_in[9];
  const float* u2wi= (const float*)d_in[10];
  const float* s1w = (const float*)d_in[11];
  const float* s1b = (const float*)d_in[12];
  const float* s2w = (const float*)d_in[13];
  const float* s2b = (const float*)d_in[14];

  k_pre    <<<192, 256>>>(v,qwr,qwi,kwr,kwi,u1wr,u1wi,s1w);
  k_mid    <<<256, 256>>>(vwr,vwi);
  k_attn_u <<<dim3(16,8,4), 256>>>();
  k_u1     <<<dim3(64,4,2), 256>>>();
  k_x1     <<<512, 256>>>(s1b);
  k_final  <<<dim3(64,4), 256>>>(u2wr,u2wi,s2w,s2b,(float*)d_out);
}

// round 17
// speedup vs baseline: 1.0827x; 1.0827x over previous
#include <cuda_runtime.h>
#include <math.h>

#define NPIX   4096
#define NMODE  64
#define NSEQ   64
#define NCH    256

typedef unsigned long long u64;

__device__ __forceinline__ u64 pk(float a, float b){
  u64 r; asm("mov.b64 %0,{%1,%2};" : "=l"(r) : "f"(a), "f"(b)); return r;
}
__device__ __forceinline__ float2 up(u64 v){
  float2 r; asm("mov.b64 {%0,%1},%2;" : "=f"(r.x), "=f"(r.y) : "l"(v)); return r;
}
__device__ __forceinline__ void fma2(u64& d, u64 a, u64 b){
  asm("fma.rn.f32x2 %0,%1,%2,%0;" : "+l"(d) : "l"(a), "l"(b));
}

// branch-free erf, Abramowitz-Stegun 7.1.26, max abs err 1.5e-7
__device__ __forceinline__ float erf_fast(float x){
  float ax = fabsf(x);
  float t  = __frcp_rn(1.0f + 0.3275911f*ax);
  float y  = t*(0.254829592f + t*(-0.284496736f + t*(1.421413741f +
             t*(-1.453152027f + t*1.061405429f))));
  float r  = 1.0f - y*__expf(-ax*ax);
  return copysignf(r, x);
}

// ---------------- scratch ----------------
__device__ __align__(16) float2 g_vf [NSEQ*4*NMODE];
__device__ __align__(16) float2 g_G2 [8*8*64*16];
__device__ __align__(16) float  g_l2s[16*32*32];
__device__ __align__(16) float2 g_vlf[NSEQ*NCH*NMODE];
__device__ __align__(16) float2 g_ufT[NCH*NMODE*NSEQ];  // [ch][m][n]
__device__ __align__(16) float2 g_w1t[NMODE*NCH*32];    // [m][ci][co], P-scaled
__device__ __align__(16) float  g_s1t[NCH*32];          // [ci][co]
__device__ __align__(16) float2 g_uf2p[2][NSEQ*NMODE*32];  // partials, [n][m][co]
__device__ __align__(16) float2 g_sk1p[2][NSEQ*NMODE*32];
__device__ __align__(16) float  g_x1 [NSEQ*32*NPIX];
__device__ __align__(16) float2 g_x1f[NSEQ*32*NMODE];

__device__ __forceinline__ void tw_init(float* twc, float* tws, u64* twp, int tid){
  if (tid < 64){
    float a = 0.09817477042468103f * (float)tid;
    float cc = cosf(a), ss = sinf(a);
    twc[tid]=cc; tws[tid]=ss;
    if (twp) twp[tid]=pk(cc,ss);
  }
}

// ---------------- K1: fwd DFT of v (0-63) + G matrix (64-127) + weight transpose (128-191) ----
__global__ __launch_bounds__(256) void k_pre(const float* __restrict__ v,
                      const float* __restrict__ qwr, const float* __restrict__ qwi,
                      const float* __restrict__ kwr, const float* __restrict__ kwi,
                      const float* __restrict__ u1wr, const float* __restrict__ u1wi,
                      const float* __restrict__ s1w){
  int tid = threadIdx.x;
  if (blockIdx.x < 64){
    __shared__ float twc[64], tws[64];
    __shared__ u64   twp[64];
    __shared__ float2 sC[4*8*64];
    int chv=tid>>6, c=tid&63;
    tw_init(twc,tws,twp,tid);
    __syncthreads();
    const float* x = v + (size_t)(blockIdx.x*4 + chv)*NPIX + c;
    u64 C2[8];
    #pragma unroll
    for (int ky=0;ky<8;ky++) C2[ky]=0ull;
    for (int r=0;r<64;r++){
      float xv = __ldg(x + r*64);
      u64 x2 = pk(xv,xv);
      #pragma unroll
      for (int ky=0;ky<8;ky++) fma2(C2[ky], x2, twp[(ky*r)&63]);
    }
    #pragma unroll
    for (int ky=0;ky<8;ky++) sC[(chv*8+ky)*64 + c] = up(C2[ky]);
    __syncthreads();
    {
      int md = tid&63, ky2 = md>>3, kx = md&7;
      float re=0.f, im=0.f;
      const float2* Crow = sC + (chv*8+ky2)*64;
      #pragma unroll 8
      for (int cc=0;cc<64;cc++){
        float2 t = Crow[cc];
        int j=(kx*cc)&63;
        re += t.x*twc[j] - t.y*tws[j];
        im -= t.y*twc[j] + t.x*tws[j];
      }
      g_vf[(size_t)(blockIdx.x*4+chv)*64 + md] = make_float2(re,im);
    }
  } else if (blockIdx.x < 128){
    int bid2 = blockIdx.x - 64;
    int gq = bid2>>3, gk = bid2&7;
    __shared__ float2 sQ[4][32][8];
    __shared__ float2 sK[4][32][8];
    for (int mc=0;mc<8;mc++){
      __syncthreads();
      int mb = mc*8;
      for (int i=tid;i<1024;i+=256){
        int ci=i>>8, d=(i>>3)&31, mm=i&7;
        int iq = (ci*256 + gq*32+d)*64 + mb+mm;
        int ik = (ci*256 + gk*32+d)*64 + mb+mm;
        sQ[ci][d][mm] = make_float2(qwr[iq], qwi[iq]);
        sK[ci][d][mm] = make_float2(kwr[ik], kwi[ik]);
      }
      __syncthreads();
      if (tid < 128){
        int mm = tid>>4, ci=(tid>>2)&3, cj=tid&3;
        int m = mb+mm;
        float re=0.f, im=0.f;
        if (m==0){
          #pragma unroll 8
          for (int d=0;d<32;d++) re += sQ[ci][d][0].x * sK[cj][d][0].x;
        } else {
          #pragma unroll 8
          for (int d=0;d<32;d++){
            float2 q=sQ[ci][d][mm], kk=sK[cj][d][mm];
            re += q.x*kk.x + q.y*kk.y;
            im += q.y*kk.x - q.x*kk.y;
          }
          float wm = ((m&7)==0) ? 0.5f : 2.0f;
          re*=wm; im*=wm;
        }
        g_G2[((size_t)(gq*8+gk)*64 + m)*16 + ci*4+cj] = make_float2(re,im);
      }
    }
  } else {
    int m = blockIdx.x - 128;
    bool kx0 = ((m&7)==0), m0 = (m==0);
    float pm = (!m0 && kx0) ? 0.5f : 1.0f;
    for (int idx=tid; idx<8192; idx+=256){
      int ci = idx>>5, co = idx&31;
      int widx = (ci*32+co)*64 + m;
      g_w1t[(size_t)(m*256+ci)*32+co] = make_float2(u1wr[widx]*pm, u1wi[widx]*pm);
    }
    if (m==0){
      for (int idx=tid; idx<8192; idx+=256){
        int ci = idx>>5, co = idx&31;
        g_s1t[ci*32+co] = s1w[co*256+ci];
      }
    }
  }
}

// ---------------- K2: vmix (blocks 0-63) + attention scores (blocks 64-191) ----------------
__global__ __launch_bounds__(256) void k_mid(const float* __restrict__ vwr, const float* __restrict__ vwi){
  int tid=threadIdx.x;
  if (blockIdx.x < 64){
    int ng = blockIdx.x>>2, cog = blockIdx.x&3;
    __shared__ float2 sv[1024];
    int n0 = ng*4;
    for (int i=tid;i<1024;i+=256) sv[i] = g_vf[(size_t)n0*256 + i];
    __syncthreads();
    for (int p=tid; p<2048; p+=256){
      int co_l = p>>5, m2 = p&31, m = m2*2;
      int co = cog*64 + co_l;
      float2 wrv[4], wiv[4];
      #pragma unroll
      for (int ci=0;ci<4;ci++){
        int wix = ((ci<<8)+co)*64 + m;
        wrv[ci] = *(const float2*)&vwr[wix];
        wiv[ci] = *(const float2*)&vwi[wix];
      }
      #pragma unroll
      for (int nl=0;nl<4;nl++){
        float re0=0.f,im0=0.f,re1=0.f,im1=0.f;
        #pragma unroll
        for (int ci=0;ci<4;ci++){
          float2 a0 = sv[nl*256+ci*64+m], a1 = sv[nl*256+ci*64+m+1];
          re0 += a0.x*wrv[ci].x - a0.y*wiv[ci].x;  im0 += a0.x*wiv[ci].x + a0.y*wrv[ci].x;
          re1 += a1.x*wrv[ci].y - a1.y*wiv[ci].y;  im1 += a1.x*wiv[ci].y + a1.y*wrv[ci].y;
        }
        float4 st = make_float4(re0,im0,re1,im1);
        *(float4*)&g_vlf[(size_t)(n0+nl)*16384 + co*64 + m] = st;
      }
    }
  } else {
    int idx = blockIdx.x - 64;
    int bh = idx>>3, g1 = idx&7;
    int b = bh>>3, hh = bh&7;
    int nbase = b*32 + hh*4;
    int g2 = tid>>5, lane = tid&31;
    const u64* Vf = (const u64*)g_vf;
    const u64* Gp = (const u64*)g_G2 + (size_t)(g1*8+g2)*1024;
    u64 sc[4][4];
    #pragma unroll
    for (int j1=0;j1<4;j1++)
      #pragma unroll
      for (int i2=0;i2<4;i2++) sc[j1][i2]=0ull;
    #pragma unroll
    for (int ml=0; ml<2; ml++){
      int m = lane*2 + ml;
      u64 vfl[4][4];
      #pragma unroll
      for (int j=0;j<4;j++)
        #pragma unroll
        for (int ci=0;ci<4;ci++)
          vfl[j][ci] = Vf[(size_t)(nbase+j)*256 + ci*64 + m];
      u64 Gl[4][4];
      #pragma unroll
      for (int ci=0;ci<4;ci++)
        #pragma unroll
        for (int cj=0;cj<4;cj++)
          Gl[ci][cj] = Gp[m*16 + ci*4 + cj];
      u64 Wl[4][4];
      #pragma unroll
      for (int i2=0;i2<4;i2++)
        #pragma unroll
        for (int ci=0;ci<4;ci++){
          float re=0.f, im=0.f;
          #pragma unroll
          for (int cj=0;cj<4;cj++){
            float2 vv = up(vfl[i2][cj]);
            float2 gg = up(Gl[ci][cj]);
            re += vv.x*gg.x + vv.y*gg.y;
            im += vv.x*gg.y - vv.y*gg.x;
          }
          Wl[i2][ci] = pk(re, -im);
        }
      #pragma unroll
      for (int j1=0;j1<4;j1++)
        #pragma unroll
        for (int i2=0;i2<4;i2++)
          #pragma unroll
          for (int ci=0;ci<4;ci++)
            fma2(sc[j1][i2], vfl[j1][ci], Wl[i2][ci]);
    }
    float scf[16];
    #pragma unroll
    for (int j1=0;j1<4;j1++)
      #pragma unroll
      for (int i2=0;i2<4;i2++){
        float2 a = up(sc[j1][i2]);
        float s = a.x + a.y;
        #pragma unroll
        for (int o=16;o;o>>=1) s += __shfl_xor_sync(0xffffffffu, s, o);
        scf[j1*4+i2] = s;
      }
    if (lane < 16){
      int j1 = lane>>2, i2 = lane&3;
      g_l2s[bh*1024 + (j1*8+g1)*32 + i2*8+g2] = scf[lane];
    }
  }
}

// ---------------- K3: fused softmax + U = A @ val, transposed output ----------------
__global__ __launch_bounds__(256) void k_attn_u(){
  int bh = blockIdx.x, dg = blockIdx.y, sg = blockIdx.z;
  int b = bh>>3, hh = bh&7;
  const float2* Vh = g_vlf + (size_t)(b*32 + hh*4)*16384;
  __shared__ float  sL [512];
  __shared__ float2 sA2[512];
  int tid = threadIdx.x;
  for (int i=tid;i<512;i+=256){
    int sl=i>>5, t=i&31;
    sL[i] = g_l2s[bh*1024 + (sg*16+sl)*32 + t] * 2.9802322387695312e-8f;
  }
  __syncthreads();
  {
    int w=tid>>5, lane=tid&31;
    #pragma unroll
    for (int rr=0;rr<2;rr++){
      int sl = w*2+rr;
      float x = sL[sl*32+lane];
      float mx = x;
      #pragma unroll
      for (int o=16;o;o>>=1) mx = fmaxf(mx, __shfl_xor_sync(0xffffffffu, mx, o));
      float e = expf(x-mx);
      float sm = e;
      #pragma unroll
      for (int o=16;o;o>>=1) sm += __shfl_xor_sync(0xffffffffu, sm, o);
      float pr = e/sm;
      sA2[sl*32+lane] = make_float2(pr,pr);
    }
  }
  __syncthreads();
  int d = dg*4 + (tid>>6);
  int m = tid&63;
  u64 acc[16];
  #pragma unroll
  for (int s=0;s<16;s++) acc[s]=0ull;
  const float2* vp = Vh + d*64 + m;
  #pragma unroll 1
  for (int t=0;t<32;t+=4){
    u64 v0 = *(const u64*)(vp + (size_t)(t+0)*2048);
    u64 v1 = *(const u64*)(vp + (size_t)(t+1)*2048);
    u64 v2 = *(const u64*)(vp + (size_t)(t+2)*2048);
    u64 v3 = *(const u64*)(vp + (size_t)(t+3)*2048);
    #pragma unroll
    for (int s=0;s<16;s++){
      fma2(acc[s], *(const u64*)&sA2[s*32+t+0], v0);
      fma2(acc[s], *(const u64*)&sA2[s*32+t+1], v1);
      fma2(acc[s], *(const u64*)&sA2[s*32+t+2], v2);
      fma2(acc[s], *(const u64*)&sA2[s*32+t+3], v3);
    }
  }
  int chb = hh*32 + d;
  float2* dst = g_ufT + ((size_t)chb*64 + m)*64 + b*32 + sg*16;
  #pragma unroll
  for (int s=0;s<16;s++) dst[s] = up(acc[s]);
}

// ---------------- K4: per-mode GEMM 256->32 (u1 with P projection) + s1 skip ----------------
// grid (64 m, 2 ns, 2 cs), 256 thr; deinterleaved A; in-register weight splats; coalesced stores
__global__ __launch_bounds__(256) void k_u1(){
  int m = blockIdx.x, ns = blockIdx.y, cs = blockIdx.z;
  bool m0 = (m==0);
  int tid = threadIdx.x, l = tid&31, w = tid>>5;
  __shared__ u64   sAx[512], sAy[512];  // [cil][pair]
  __shared__ float2 sW[1024];           // [cil][co]
  __shared__ float  sS[1024];
  u64 cRe[2]={0ull,0ull}, cIm[2]={0ull,0ull}, kRe[2]={0ull,0ull}, kIm[2]={0ull,0ull};
  int cbase = cs*128;
  for (int ci0=cbase; ci0<cbase+128; ci0+=32){
    __syncthreads();
    #pragma unroll
    for (int k=0;k<2;k++){
      int idx = tid + k*256;
      int cil = idx>>4, p = idx&15;
      float4 a2 = *(const float4*)&g_ufT[((size_t)(ci0+cil)*64 + m)*64 + ns*32 + p*2];
      sAx[cil*16+p] = pk(a2.x, a2.z);
      sAy[cil*16+p] = pk(a2.y, a2.w);
    }
    #pragma unroll
    for (int k=0;k<2;k++){
      int idx = tid + k*256;
      int cil = idx>>4, cp = idx&15;
      float4 w2 = *(const float4*)&g_w1t[(size_t)(m*256 + ci0+cil)*32 + cp*2];
      sW[cil*32 + cp*2]   = make_float2(w2.x, w2.y);
      sW[cil*32 + cp*2+1] = make_float2(w2.z, w2.w);
      float2 s2 = *(const float2*)&g_s1t[(ci0+cil)*32 + cp*2];
      sS[cil*32 + cp*2]   = s2.x;
      sS[cil*32 + cp*2+1] = s2.y;
    }
    __syncthreads();
    #pragma unroll 8
    for (int cil=0; cil<32; cil++){
      float2 wv = sW[cil*32+l];
      float swv = sS[cil*32+l];
      u64 wxs = pk(wv.x, wv.x);
      u64 wys = pk(wv.y, wv.y);
      u64 wyn = m0 ? 0ull : pk(-wv.y, -wv.y);
      u64 wxY = m0 ? 0ull : wxs;
      u64 sws = pk(swv, swv);
      #pragma unroll
      for (int j=0;j<2;j++){
        u64 X = sAx[cil*16 + w*2 + j];
        u64 Y = sAy[cil*16 + w*2 + j];
        fma2(cRe[j], X, wxs); fma2(cRe[j], Y, wyn);
        fma2(cIm[j], X, wys); fma2(cIm[j], Y, wxY);
        fma2(kRe[j], X, sws);
        fma2(kIm[j], Y, sws);
      }
    }
  }
  float2* uf2 = g_uf2p[cs];
  float2* sk1 = g_sk1p[cs];
  #pragma unroll
  for (int j=0;j<2;j++){
    float2 re=up(cRe[j]), im=up(cIm[j]);
    float2 sre=up(kRe[j]), sim=up(kIm[j]);
    int n0 = ns*32 + w*4 + 2*j;
    uf2[((size_t)(n0  )*64+m)*32+l] = make_float2(re.x, im.x);
    uf2[((size_t)(n0+1)*64+m)*32+l] = make_float2(re.y, im.y);
    sk1[((size_t)(n0  )*64+m)*32+l] = make_float2(sre.x, sim.x);
    sk1[((size_t)(n0+1)*64+m)*32+l] = make_float2(sre.y, sim.y);
  }
}

// ---------------- K5: synthesis + gelu + skip -> x1, fused forward DFT -> x1f ----------------
__global__ __launch_bounds__(256) void k_x1(const float* __restrict__ s1b){
  __shared__ float twc[64], tws[64];
  __shared__ u64   twp[64];
  __shared__ float2 sF1[256], sF2[256];
  __shared__ float2 sC[4*8*64];
  int tid=threadIdx.x, chv=tid>>6, c=tid&63;
  int n = blockIdx.x>>3, cg = blockIdx.x&7;
  int ch = cg*4 + chv;
  tw_init(twc,tws,twp,tid);
  {
    int chl = tid&3, mm = tid>>2;
    size_t ix = ((size_t)n*64 + mm)*32 + cg*4 + chl;
    float2 a0 = g_uf2p[0][ix], a1 = g_uf2p[1][ix];
    sF1[mm*4+chl] = make_float2(a0.x+a1.x, a0.y+a1.y);
    float2 b0 = g_sk1p[0][ix], b1 = g_sk1p[1][ix];
    sF2[mm*4+chl] = make_float2(b0.x+b1.x, b0.y+b1.y);
  }
  __syncthreads();
  u64 U1p[8], U2p[8];
  #pragma unroll
  for (int ky=0;ky<8;ky++){
    float2 f1=sF1[(ky*8)*4+chv], f2=sF2[(ky*8)*4+chv];
    float u1x=f1.x, u1y=f1.y, u2x=f2.x, u2y=f2.y;
    #pragma unroll
    for (int kx=1;kx<8;kx++){
      int j=(kx*c)&63; float tc=twc[j], ts=tws[j];
      f1=sF1[(ky*8+kx)*4+chv]; f2=sF2[(ky*8+kx)*4+chv];
      u1x += 2.f*(f1.x*tc - f1.y*ts); u1y += 2.f*(f1.x*ts + f1.y*tc);
      u2x += 2.f*(f2.x*tc - f2.y*ts); u2y += 2.f*(f2.x*ts + f2.y*tc);
    }
    U1p[ky]=pk(u1x,u1y); U2p[ky]=pk(u2x,u2y);
  }
  u64 C2[8];
  #pragma unroll
  for (int ky=0;ky<8;ky++) C2[ky]=0ull;
  float bias = s1b[ch&31];
  float* gx = g_x1 + ((size_t)n*32 + ch)*NPIX + c;
  const float inv = 1.0f/4096.0f;
  for (int r=0;r<64;r++){
    u64 wp[8];
    #pragma unroll
    for (int ky=0;ky<8;ky++) wp[ky]=twp[(ky*r)&63];
    u64 a1=0ull, a2=0ull;
    #pragma unroll
    for (int ky=0;ky<8;ky++){ fma2(a1,U1p[ky],wp[ky]); fma2(a2,U2p[ky],wp[ky]); }
    float2 v1=up(a1), v2=up(a2);
    float y1=(v1.x - v1.y)*inv;
    float y2=(v2.x - v2.y)*inv;
    float g = 0.5f*y1*(1.f+erf_fast(y1*0.70710678118654752f));
    float val = g + y2 + bias;
    gx[r*64] = val;
    u64 vp2 = pk(val,val);
    #pragma unroll
    for (int ky=0;ky<8;ky++) fma2(C2[ky], vp2, wp[ky]);
  }
  #pragma unroll
  for (int ky=0;ky<8;ky++) sC[(chv*8+ky)*64 + c] = up(C2[ky]);
  __syncthreads();
  {
    int md=tid&63, ky2=md>>3, kx=md&7;
    float re=0.f, im=0.f;
    const float2* Crow = sC + (chv*8+ky2)*64;
    #pragma unroll 8
    for (int cc=0;cc<64;cc++){
      float2 t = Crow[cc];
      int j=(kx*cc)&63;
      re += t.x*twc[j] - t.y*tws[j];
      im -= t.y*twc[j] + t.x*tws[j];
    }
    g_x1f[((size_t)n*32 + ch)*64 + md] = make_float2(re,im);
  }
}

// ---------------- K6: u2 spectral conv + synthesis + conv1x1 skip ----------------
__global__ __launch_bounds__(256) void k_final(const float* __restrict__ u2wr, const float* __restrict__ u2wi,
                        const float* __restrict__ s2w, const float* __restrict__ s2b,
                        float* __restrict__ out){
  int n = blockIdx.x;
  __shared__ float twc[64], tws[64];
  __shared__ u64   twp[64];
  __shared__ float2 sXF[2048];
  __shared__ float2 sF[256];
  __shared__ float2 T[4*512];
  __shared__ u64 sw2[128];
  __shared__ float sbv[4];
  int tid=threadIdx.x;
  tw_init(twc,tws,twp,tid);
  for (int i=tid;i<2048;i+=256) sXF[i] = g_x1f[(size_t)n*2048 + i];
  if (tid<128){ float w=s2w[tid]; sw2[tid]=pk(w,w); }
  if (tid<4) sbv[tid]=s2b[tid];
  __syncthreads();
  {
    int o=tid>>6, m=tid&63;
    float re=0.f, im=0.f;
    #pragma unroll 8
    for (int ci=0;ci<32;ci++){
      float2 a = sXF[ci*64+m];
      int wix = ((ci*4+o)<<6)+m;
      float br=u2wr[wix], bi=u2wi[wix];
      re += a.x*br - a.y*bi;
      im += a.x*bi + a.y*br;
    }
    sF[tid]=make_float2(re,im);
  }
  __syncthreads();
  for (int id=tid; id<2048; id+=256){
    int o=id>>9, rem=id&511, r=rem>>3, kx=rem&7;
    float re=0.f, im=0.f;
    #pragma unroll
    for (int ky=0;ky<8;ky++){
      int j=(ky*r)&63; float cc=twc[j], ss=tws[j];
      float2 f=sF[o*64+ky*8+kx];
      re += f.x*cc - f.y*ss; im += f.x*ss + f.y*cc;
    }
    T[id]=make_float2(re,im);
  }
  __syncthreads();
  const float4* gx4 = (const float4*)(g_x1 + (size_t)n*32*NPIX);
  float* go = out + (size_t)n*4*NPIX;
  const float inv = 1.0f/4096.0f;
  {
    int q = blockIdx.y*256 + tid;
    int p0 = q*4, r = p0>>6, cb = p0&63;
    float ybuf[4][4];
    #pragma unroll
    for (int j=0;j<4;j++){
      int cc = cb+j;
      u64 a[4]={0ull,0ull,0ull,0ull};
      #pragma unroll
      for (int kx=1;kx<8;kx++){
        u64 wv = twp[(kx*cc)&63];
        #pragma unroll
        for (int o=0;o<4;o++) fma2(a[o], *(const u64*)&T[o*512 + r*8 + kx], wv);
      }
      #pragma unroll
      for (int o=0;o<4;o++){
        float2 v = up(a[o]);
        ybuf[o][j] = T[o*512 + r*8].x + 2.f*(v.x - v.y);
      }
    }
    u64 s01[4]={0ull,0ull,0ull,0ull}, s23[4]={0ull,0ull,0ull,0ull};
    #pragma unroll 8
    for (int ci=0;ci<32;ci++){
      float4 xv = __ldg(gx4 + ci*1024 + q);
      u64 x01 = pk(xv.x,xv.y), x23 = pk(xv.z,xv.w);
      #pragma unroll
      for (int o=0;o<4;o++){
        u64 wv = sw2[o*32+ci];
        fma2(s01[o], wv, x01);
        fma2(s23[o], wv, x23);
      }
    }
    #pragma unroll
    for (int o=0;o<4;o++){
      float2 p01=up(s01[o]), p23=up(s23[o]);
      float bo = sbv[o];
      float4 r4;
      r4.x = ybuf[o][0]*inv + p01.x + bo;
      r4.y = ybuf[o][1]*inv + p01.y + bo;
      r4.z = ybuf[o][2]*inv + p23.x + bo;
      r4.w = ybuf[o][3]*inv + p23.y + bo;
      *(float4*)(go + o*NPIX + p0) = r4;
    }
  }
}

// ---------------- launch ----------------
extern "C" void kernel_launch(void* const* d_in, const int* in_sizes, int n_in,
                              void* d_out, int out_size){
  const float* v   = (const float*)d_in[0];
  const float* qwr = (const float*)d_in[1];
  const float* qwi = (const float*)d_in[2];
  const float* kwr = (const float*)d_in[3];
  const float* kwi = (const float*)d_in[4];
  const float* vwr = (const float*)d_in[5];
  const float* vwi = (const float*)d_in[6];
  const float* u1wr= (const float*)d_in[7];
  const float* u1wi= (const float*)d_in[8];
  const float* u2wr= (const float*)d_in[9];
  const float* u2wi= (const float*)d_in[10];
  const float* s1w = (const float*)d_in[11];
  const float* s1b = (const float*)d_in[12];
  const float* s2w = (const float*)d_in[13];
  const float* s2b = (const float*)d_in[14];

  k_pre    <<<192, 256>>>(v,qwr,qwi,kwr,kwi,u1wr,u1wi,s1w);
  k_mid    <<<192, 256>>>(vwr,vwi);
  k_attn_u <<<dim3(16,8,2), 256>>>();
  k_u1     <<<dim3(64,2,2), 256>>>();
  k_x1     <<<512, 256>>>(s1b);
  k_final  <<<dim3(64,4), 256>>>(u2wr,u2wi,s2w,s2b,(float*)d_out);
}